// round 15
// baseline (speedup 1.0000x reference)
#include <cuda_runtime.h>
#include <cstdint>

#define IH 120
#define IW 160
#define NPIX (IH*IW)
#define NANCH (NPIX*9)
#define PRE_NMS 6000
#define POST_NMS 300
#define NEGV (-1000000000.0f)
#define NB 94                       // ceil(6000/64) mask words per row

// ---------------- device scratch ----------------
__device__ float g_x[NPIX * 512];            // conv1 output, [pixel][channel]
__device__ float g_props[NANCH * 4];
__device__ unsigned long long g_keys[NANCH];
__device__ unsigned long long g_cand[PRE_NMS + 64];
__device__ unsigned long long g_sorted[PRE_NMS + 64];
__device__ unsigned int g_hist[256];
__device__ unsigned long long g_prefix;
__device__ int g_rank;
__device__ unsigned int g_counter;
__device__ unsigned long long g_mask[(size_t)PRE_NMS * NB];  // suppression bitmasks
__device__ float g_bx[PRE_NMS * 4];          // sorted, decoded boxes
__device__ float g_ar[PRE_NMS];              // areas
__device__ int g_nvalid;                     // first index with score <= NEG/2

__constant__ float c_anch[9][4] = {
    {-84.f,  -40.f,  99.f,  55.f},
    {-176.f, -88.f,  191.f, 103.f},
    {-360.f, -184.f, 375.f, 199.f},
    {-56.f,  -56.f,  71.f,  71.f},
    {-120.f, -120.f, 135.f, 135.f},
    {-248.f, -248.f, 263.f, 263.f},
    {-36.f,  -80.f,  51.f,  95.f},
    {-80.f,  -168.f, 95.f,  183.f},
    {-168.f, -344.f, 183.f, 359.f}
};

// ---------------- pre-kernels (state init; also put conv at ncu slot 5) ----------------
__global__ void init1() { g_prefix = 0ull; g_rank = PRE_NMS; }
__global__ void init2() { g_counter = 0u; g_nvalid = PRE_NMS; }
__global__ __launch_bounds__(256) void zero_hist() { g_hist[threadIdx.x] = 0u; }

// ---------------- stage 1: 3x3 conv 512->512 + bias + relu ----------------
// Per-output FMA chain is EXACTLY the verified order (ic chunks of 16 ascending
// -> icl -> ky -> kx, serial fmaf) => g_x bit-identical, rel_err == 2.417291e-07.
// FULLY UNROLLED inner block: all smem addresses fold to base_reg + immediate,
// eliminating the ~21 IMAD issues per (icl,ky) ncu attributed to the alu pipe.
#define WS 68   // [ick][oc] stride; multiple of 4 => 16B-aligned float4 loads
__global__ __launch_bounds__(256) void conv3x3_relu(
    const float* __restrict__ feat,   // [512][120][160]
    const float* __restrict__ wgt,    // [512][512][3][3]
    const float* __restrict__ bias)   // [512]
{
    __shared__ float s_w[144 * WS];       // [ick 0..143][oc 0..63]
    __shared__ float s_in[16 * 4 * 38];   // [icl][row 0..3] stride 38 (cols 0..33)

    const int tid = threadIdx.x;
    const int bx = blockIdx.x, by = blockIdx.y;
    const int oc0 = blockIdx.z * 64;
    const int pg = tid & 15, og = tid >> 4;
    const int r = pg >> 3, c0 = (pg & 7) << 2;
    const int h0 = by * 2, w0 = bx * 32;
    const int ogb = og << 2;

    // per-thread constant bases (computed once; inner loop uses immediates)
    const float* in_base = &s_in[r * 38 + c0];
    const float* w_base  = &s_w[ogb];

    float acc[4][4];
#pragma unroll
    for (int o = 0; o < 4; o++)
#pragma unroll
        for (int j = 0; j < 4; j++) acc[o][j] = 0.f;

    for (int ic0 = 0; ic0 < 512; ic0 += 16) {
        // ---- input tile: 16 ic x 4 rows x 34 cols (zero padded) ----
        for (int idx = tid; idx < 16 * 136; idx += 256) {
            int icl = idx / 136;
            int rem = idx - icl * 136;
            int rr = rem / 34;
            int cc = rem - rr * 34;
            int gh = h0 - 1 + rr;
            int gc = w0 - 1 + cc;
            float v = 0.f;
            if (gh >= 0 && gh < IH && gc >= 0 && gc < IW)
                v = feat[(ic0 + icl) * NPIX + gh * IW + gc];
            s_in[(icl * 4 + rr) * 38 + cc] = v;
        }
        // ---- weights: coalesced read per oc row, transposed store [ick][oc] ----
        for (int idx = tid; idx < 64 * 144; idx += 256) {
            int ocl = idx / 144;
            int ick = idx - ocl * 144;
            s_w[ick * WS + ocl] = wgt[(oc0 + ocl) * 4608 + ic0 * 9 + ick];
        }
        __syncthreads();

#pragma unroll
        for (int icl = 0; icl < 16; icl++) {
#pragma unroll
            for (int ky = 0; ky < 3; ky++) {
                float xin[6];
#pragma unroll
                for (int t = 0; t < 6; t++)
                    xin[t] = in_base[(icl * 4 + ky) * 38 + t];   // imm offset
#pragma unroll
                for (int kx = 0; kx < 3; kx++) {
                    const int ick = icl * 9 + ky * 3 + kx;       // compile-time
                    const float4 w4 = *(const float4*)&w_base[ick * WS];
#pragma unroll
                    for (int j = 0; j < 4; j++) {
                        float xv = xin[kx + j];
                        acc[0][j] = fmaf(w4.x, xv, acc[0][j]);
                        acc[1][j] = fmaf(w4.y, xv, acc[1][j]);
                        acc[2][j] = fmaf(w4.z, xv, acc[2][j]);
                        acc[3][j] = fmaf(w4.w, xv, acc[3][j]);
                    }
                }
            }
        }
        __syncthreads();
    }

    const int gh = h0 + r;
    float b0 = bias[oc0 + ogb + 0];
    float b1 = bias[oc0 + ogb + 1];
    float b2 = bias[oc0 + ogb + 2];
    float b3 = bias[oc0 + ogb + 3];
#pragma unroll
    for (int j = 0; j < 4; j++) {
        int gw = w0 + c0 + j;
        float4 v;
        v.x = fmaxf(acc[0][j] + b0, 0.f);
        v.y = fmaxf(acc[1][j] + b1, 0.f);
        v.z = fmaxf(acc[2][j] + b2, 0.f);
        v.w = fmaxf(acc[3][j] + b3, 0.f);
        *(float4*)&g_x[(size_t)(gh * IW + gw) * 512 + oc0 + ogb] = v;
    }
}

// ---------------- stage 2: 1x1 heads + softmax + anchor decode ----------------
#define HEAD_SMEM ((54 * 513 + 16 * 512 + 16 * 64) * 4)

__global__ __launch_bounds__(1024) void head_kernel(
    const float* __restrict__ im_info,
    const float* __restrict__ sw, const float* __restrict__ sb,
    const float* __restrict__ bw, const float* __restrict__ bb)
{
    extern __shared__ float sm[];
    float* s_w = sm;                       // 54*513
    float* s_x = sm + 54 * 513;            // 16*512
    float* s_o = s_x + 16 * 512;           // 16*64

    const int tid = threadIdx.x;
    const int p0 = blockIdx.x * 16;

    for (int idx = tid; idx < 54 * 512; idx += 1024) {
        int oc = idx >> 9, c = idx & 511;
        float v = (oc < 18) ? sw[oc * 512 + c] : bw[(oc - 18) * 512 + c];
        s_w[oc * 513 + c] = v;
    }
    for (int idx = tid; idx < 16 * 512; idx += 1024)
        s_x[idx] = g_x[(size_t)p0 * 512 + idx];
    __syncthreads();

    const int px = tid >> 6, oc = tid & 63;
    if (oc < 54) {
        float acc = 0.f;
        const float* xr = &s_x[px * 512];
        const float* wr = &s_w[oc * 513];
#pragma unroll 8
        for (int c = 0; c < 512; c++) acc = fmaf(xr[c], wr[c], acc);
        acc += (oc < 18) ? sb[oc] : bb[oc - 18];
        s_o[px * 64 + oc] = acc;
    }
    __syncthreads();

    if (tid < 144) {
        const int lpx = tid / 9, a = tid - lpx * 9;
        const float* row = &s_o[lpx * 64];
        float m = row[0];
#pragma unroll
        for (int i = 1; i < 18; i++) m = fmaxf(m, row[i]);
        float den = 0.f;
#pragma unroll
        for (int i = 0; i < 18; i++) den += expf(row[i] - m);
        float prob = expf(row[9 + a] - m) / den;

        float dx = row[18 + a * 4 + 0];
        float dy = row[18 + a * 4 + 1];
        float dw = row[18 + a * 4 + 2];
        float dh = row[18 + a * 4 + 3];

        const int p = p0 + lpx;
        const int hh = p / IW, ww = p - hh * IW;
        const float sx = ww * 16.f, sy = hh * 16.f;
        float ax1 = c_anch[a][0] + sx, ay1 = c_anch[a][1] + sy;
        float ax2 = c_anch[a][2] + sx, ay2 = c_anch[a][3] + sy;
        float aw = ax2 - ax1 + 1.f, ah = ay2 - ay1 + 1.f;
        float cx = ax1 + 0.5f * aw, cy = ay1 + 0.5f * ah;
        float pcx = dx * aw + cx, pcy = dy * ah + cy;
        float pw = expf(dw) * aw, ph = expf(dh) * ah;
        float x1 = pcx - 0.5f * pw, y1 = pcy - 0.5f * ph;
        float x2 = pcx + 0.5f * pw, y2 = pcy + 0.5f * ph;

        const float imh = im_info[0], imw = im_info[1], iscale = im_info[2];
        x1 = fminf(fmaxf(x1, 0.f), imw - 1.f);
        x2 = fminf(fmaxf(x2, 0.f), imw - 1.f);
        y1 = fminf(fmaxf(y1, 0.f), imh - 1.f);
        y2 = fminf(fmaxf(y2, 0.f), imh - 1.f);

        float wsv = x2 - x1 + 1.f, hsv = y2 - y1 + 1.f;
        bool keep = (wsv >= 16.f * iscale) && (hsv >= 16.f * iscale);
        float sc = keep ? prob : NEGV;

        const int gi = p * 9 + a;
        g_props[gi * 4 + 0] = x1;
        g_props[gi * 4 + 1] = y1;
        g_props[gi * 4 + 2] = x2;
        g_props[gi * 4 + 3] = y2;

        unsigned int u = __float_as_uint(sc);
        u = (u & 0x80000000u) ? ~u : (u | 0x80000000u);
        g_keys[gi] = ((unsigned long long)u << 32) | (unsigned int)(~(unsigned int)gi);
    }
}

// ---------------- stage 3: exact 64-bit radix select ----------------
__global__ __launch_bounds__(256) void hist_pass(int pass) {
    __shared__ unsigned int sh[256];
    if (threadIdx.x < 256) sh[threadIdx.x] = 0u;
    __syncthreads();
    const unsigned long long prefix = g_prefix;
    const int shift = pass * 8;
    for (int i = blockIdx.x * blockDim.x + threadIdx.x; i < NANCH; i += gridDim.x * blockDim.x) {
        unsigned long long k = g_keys[i];
        bool match = (pass == 7) || ((k >> (shift + 8)) == prefix);
        if (match) atomicAdd(&sh[(unsigned int)(k >> shift) & 255u], 1u);
    }
    __syncthreads();
    if (threadIdx.x < 256 && sh[threadIdx.x]) atomicAdd(&g_hist[threadIdx.x], sh[threadIdx.x]);
}

__global__ __launch_bounds__(256) void select_pass(int pass) {
    __shared__ unsigned int c[256];
    const int d = threadIdx.x;
    c[d] = g_hist[d];
    __syncthreads();
#pragma unroll
    for (int off = 1; off < 256; off <<= 1) {
        unsigned int add = (d + off < 256) ? c[d + off] : 0u;
        __syncthreads();
        c[d] += add;
        __syncthreads();
    }
    const unsigned int rank = (unsigned int)g_rank;
    unsigned int cumd  = c[d];
    unsigned int cumd1 = (d < 255) ? c[d + 1] : 0u;
    if (cumd >= rank && cumd1 < rank) {
        g_prefix = (g_prefix << 8) | (unsigned long long)d;
        g_rank = (int)(rank - cumd1);
        if (pass == 0) g_counter = 0u;
    }
    g_hist[d] = 0u;
}

__global__ __launch_bounds__(256) void compact_k() {
    const unsigned long long T = g_prefix;  // exact rank-6000 key (keys unique)
    for (int i = blockIdx.x * blockDim.x + threadIdx.x; i < NANCH; i += gridDim.x * blockDim.x) {
        unsigned long long k = g_keys[i];
        if (k >= T) {
            unsigned int p = atomicAdd(&g_counter, 1u);
            if (p < PRE_NMS) g_cand[p] = k;
        }
    }
}

// ---------------- stage 4: bitonic sort of 6000 (pad 8192) ----------------
__global__ __launch_bounds__(1024) void sort_k() {
    extern __shared__ unsigned long long sk[];  // 8192 * 8B = 64 KB
    const int tid = threadIdx.x;
    for (int i = tid; i < 8192; i += 1024)
        sk[i] = (i < PRE_NMS) ? g_cand[i] : 0ull;
    __syncthreads();
    for (int k = 2; k <= 8192; k <<= 1) {
        for (int j = k >> 1; j > 0; j >>= 1) {
            for (int t = tid; t < 4096; t += 1024) {
                int i = (t << 1) - (t & (j - 1));
                int l = i + j;
                unsigned long long a = sk[i], b = sk[l];
                bool desc = ((i & k) == 0);
                if ((a < b) == desc) { sk[i] = b; sk[l] = a; }
            }
            __syncthreads();
        }
    }
    for (int i = tid; i < PRE_NMS; i += 1024) g_sorted[i] = sk[i];
}

// ---------------- stage 5a: decode sorted keys -> boxes/areas/nvalid ----------------
__global__ __launch_bounds__(1024) void decode_k() {
    int i = blockIdx.x * 1024 + threadIdx.x;
    if (i >= PRE_NMS) return;
    unsigned long long k = g_sorted[i];
    unsigned int idx = ~(unsigned int)(k & 0xffffffffull);
    unsigned int u = (unsigned int)(k >> 32);
    unsigned int ob = (u & 0x80000000u) ? (u & 0x7fffffffu) : ~u;
    float sc = __uint_as_float(ob);
    float a0 = g_props[idx * 4 + 0];
    float a1 = g_props[idx * 4 + 1];
    float a2 = g_props[idx * 4 + 2];
    float a3 = g_props[idx * 4 + 3];
    g_bx[i * 4 + 0] = a0;
    g_bx[i * 4 + 1] = a1;
    g_bx[i * 4 + 2] = a2;
    g_bx[i * 4 + 3] = a3;
    g_ar[i] = (a2 - a0 + 1.f) * (a3 - a1 + 1.f);
    if (!(sc > NEGV * 0.5f)) atomicMin(&g_nvalid, i);
}

// ---------------- stage 5b: all-pairs suppression masks ----------------
__global__ __launch_bounds__(64) void mask_k() {
    const int jb = blockIdx.x, ib = blockIdx.y;
    const int t = threadIdx.x;
    __shared__ float jx1[64], jy1[64], jx2[64], jy2[64], jar[64];

    const int j0 = jb * 64;
    const int jn = min(64, PRE_NMS - j0);
    if (t < jn) {
        jx1[t] = g_bx[(j0 + t) * 4 + 0];
        jy1[t] = g_bx[(j0 + t) * 4 + 1];
        jx2[t] = g_bx[(j0 + t) * 4 + 2];
        jy2[t] = g_bx[(j0 + t) * 4 + 3];
        jar[t] = g_ar[j0 + t];
    }
    __syncthreads();

    const int i = ib * 64 + t;
    if (i >= PRE_NMS) return;
    unsigned long long bits = 0ull;
    if (jb >= ib) {   // lower-triangle blocks: all j <= i -> bits stay 0
        float x1 = g_bx[i * 4 + 0], y1 = g_bx[i * 4 + 1];
        float x2 = g_bx[i * 4 + 2], y2 = g_bx[i * 4 + 3];
        float a  = g_ar[i];
        for (int jj = 0; jj < jn; jj++) {
            if (j0 + jj > i) {
                float xx1 = fmaxf(x1, jx1[jj]);
                float yy1 = fmaxf(y1, jy1[jj]);
                float xx2 = fminf(x2, jx2[jj]);
                float yy2 = fminf(y2, jy2[jj]);
                float inter = fmaxf(xx2 - xx1 + 1.f, 0.f) * fmaxf(yy2 - yy1 + 1.f, 0.f);
                float iou = inter / (a + jar[jj] - inter);
                if (iou > 0.7f) bits |= (1ull << jj);
            }
        }
    }
    g_mask[(size_t)i * NB + jb] = bits;
}

// ---------------- stage 5c: single-warp greedy collect ----------------
__global__ __launch_bounds__(32) void collect_k(float* __restrict__ out) {
    const int lane = threadIdx.x;                 // 32 threads, one warp
    unsigned long long rem[3] = {0ull, 0ull, 0ull};  // lane owns words lane, lane+32, lane+64
    const int nvalid = g_nvalid;
    int kept = 0;
    int w = 0;
    while (w < NB && kept < POST_NMS) {
        const int owner = w & 31, slot = w >> 5;
        long long hi = (long long)nvalid - (long long)w * 64;
        unsigned long long vm = (hi <= 0) ? 0ull : (hi >= 64 ? ~0ull : ((1ull << hi) - 1ull));
        unsigned long long mine = rem[slot];
        unsigned long long live = __shfl_sync(0xffffffffu, ~mine, owner) & vm;
        if (live == 0ull) { w++; continue; }
        const int b = __ffsll((long long)live) - 1;
        const int i = w * 64 + b;
        if (lane == 0) out[kept * 5 + 0] = 0.f;
        if (lane >= 1 && lane <= 4) out[kept * 5 + lane] = g_bx[i * 4 + (lane - 1)];
        kept++;
#pragma unroll
        for (int s = 0; s < 3; s++) {
            int wd = lane + 32 * s;
            if (wd < NB) rem[s] |= g_mask[(size_t)i * NB + wd];
        }
        if (lane == owner) rem[slot] |= (1ull << b);
    }
    for (int q = kept * 5 + lane; q < POST_NMS * 5; q += 32) out[q] = 0.f;
}

// ---------------- launch ----------------
extern "C" void kernel_launch(void* const* d_in, const int* in_sizes, int n_in,
                              void* d_out, int out_size) {
    const float* feat    = (const float*)d_in[0];
    const float* im_info = (const float*)d_in[1];
    const float* c1w     = (const float*)d_in[2];
    const float* c1b     = (const float*)d_in[3];
    const float* sw      = (const float*)d_in[4];
    const float* sb      = (const float*)d_in[5];
    const float* bw      = (const float*)d_in[6];
    const float* bb      = (const float*)d_in[7];
    float* out = (float*)d_out;

    cudaFuncSetAttribute(head_kernel, cudaFuncAttributeMaxDynamicSharedMemorySize, HEAD_SMEM);
    cudaFuncSetAttribute(sort_k, cudaFuncAttributeMaxDynamicSharedMemorySize, 8192 * 8);

    // 3 pre-kernels: state init + aligns ncu (-s 5, 2 harness launches) onto conv
    init1<<<1, 1>>>();
    init2<<<1, 1>>>();
    zero_hist<<<1, 256>>>();

    conv3x3_relu<<<dim3(5, 60, 8), 256>>>(feat, c1w, c1b);
    head_kernel<<<NPIX / 16, 1024, HEAD_SMEM>>>(im_info, sw, sb, bw, bb);
    for (int pass = 7; pass >= 0; pass--) {
        hist_pass<<<256, 256>>>(pass);
        select_pass<<<1, 256>>>(pass);
    }
    compact_k<<<128, 256>>>();
    sort_k<<<1, 1024, 8192 * 8>>>();
    decode_k<<<(PRE_NMS + 1023) / 1024, 1024>>>();
    mask_k<<<dim3(NB, NB), 64>>>();
    collect_k<<<1, 32>>>(out);
}

// round 16
// speedup vs baseline: 1.1032x; 1.1032x over previous
#include <cuda_runtime.h>
#include <cstdint>

#define IH 120
#define IW 160
#define NPIX (IH*IW)
#define NANCH (NPIX*9)
#define PRE_NMS 6000
#define POST_NMS 300
#define NEGV (-1000000000.0f)
#define NB 94                       // ceil(6000/64) mask words per row

// ---------------- device scratch ----------------
__device__ float g_x[NPIX * 512];            // conv1 output, [pixel][channel]
__device__ float g_props[NANCH * 4];
__device__ unsigned long long g_keys[NANCH];
__device__ unsigned long long g_cand[PRE_NMS + 64];
__device__ unsigned long long g_sorted[PRE_NMS + 64];
__device__ unsigned int g_hist[256];
__device__ unsigned long long g_prefix;
__device__ int g_rank;
__device__ unsigned int g_counter;
__device__ unsigned long long g_mask[(size_t)PRE_NMS * NB];  // suppression bitmasks
__device__ float g_bx[PRE_NMS * 4];          // sorted, decoded boxes
__device__ float g_ar[PRE_NMS];              // areas
__device__ int g_nvalid;                     // first index with score <= NEG/2

__constant__ float c_anch[9][4] = {
    {-84.f,  -40.f,  99.f,  55.f},
    {-176.f, -88.f,  191.f, 103.f},
    {-360.f, -184.f, 375.f, 199.f},
    {-56.f,  -56.f,  71.f,  71.f},
    {-120.f, -120.f, 135.f, 135.f},
    {-248.f, -248.f, 263.f, 263.f},
    {-36.f,  -80.f,  51.f,  95.f},
    {-80.f,  -168.f, 95.f,  183.f},
    {-168.f, -344.f, 183.f, 359.f}
};

// ---------------- pre-kernels (state init; also put conv at ncu slot 5) ----------------
__global__ void init1() { g_prefix = 0ull; g_rank = PRE_NMS; }
__global__ void init2() { g_counter = 0u; g_nvalid = PRE_NMS; }
__global__ __launch_bounds__(256) void zero_hist() { g_hist[threadIdx.x] = 0u; }

// ---------------- stage 1: 3x3 conv 512->512 + bias + relu ----------------
// Per-output FMA chain is EXACTLY the verified order (ic chunks of 16 ascending
// -> icl -> ky -> kx, serial fmaf) => g_x bit-identical, rel_err == 2.417291e-07.
// NEW: div-free staging loops (no /136, /34, /144 per element). The ~500
// ALU-ops/chunk/thread of index math (ncu: alu pipe 22%) collapse to ~150.
#define WS 68   // [ick][oc] stride; multiple of 4 => 16B-aligned float4 loads
__global__ __launch_bounds__(256) void conv3x3_relu(
    const float* __restrict__ feat,   // [512][120][160]
    const float* __restrict__ wgt,    // [512][512][3][3]
    const float* __restrict__ bias)   // [512]
{
    __shared__ float s_w[144 * WS];       // [ick 0..143][oc 0..63]
    __shared__ float s_in[16 * 4 * 38];   // [icl][row 0..3] stride 38 (cols 0..33)

    const int tid = threadIdx.x;
    const int bx = blockIdx.x, by = blockIdx.y;
    const int oc0 = blockIdx.z * 64;
    const int pg = tid & 15, og = tid >> 4;
    const int r = pg >> 3, c0 = (pg & 7) << 2;
    const int h0 = by * 2, w0 = bx * 32;
    const int ogb = og << 2;
    const int wid = tid >> 5, lane = tid & 31;

    float acc[4][4];
#pragma unroll
    for (int o = 0; o < 4; o++)
#pragma unroll
        for (int j = 0; j < 4; j++) acc[o][j] = 0.f;

    // per-thread constant staging bases (no div/mod anywhere in the chunk loop)
    const int icl_a = tid >> 5;           // this thread stages icl_a and icl_a+8
    const float* in_src0 = feat + (size_t)icl_a * NPIX + (h0 - 1) * IW + (w0 - 1);
    float* in_dst0 = &s_in[icl_a * 4 * 38];

    const float* w_src0 = wgt + (size_t)(oc0 + wid) * 4608;   // row wid, advance +8 rows
    // compute bases
    const float* in_base = &s_in[r * 38 + c0];
    const float* w_base  = &s_w[ogb];

    for (int ic0 = 0; ic0 < 512; ic0 += 16) {
        // ---- input tile: 16 ic x 4 rows x 34 cols (zero padded), div-free ----
        {
            const float* srcA = in_src0 + (size_t)ic0 * NPIX;
#pragma unroll
            for (int half = 0; half < 2; half++) {
                const int icl = icl_a + half * 8;
                const float* src = srcA + (size_t)(half * 8) * NPIX;
                float* dst = in_dst0 + half * 8 * 4 * 38;
#pragma unroll
                for (int rr = 0; rr < 4; rr++) {
                    const int gh = h0 - 1 + rr;
                    const bool ghok = (gh >= 0 && gh < IH);
#pragma unroll
                    for (int k = 0; k < 2; k++) {
                        const int cc = lane + 32 * k;
                        if (cc < 34) {
                            const int gc = w0 - 1 + cc;
                            float v = 0.f;
                            if (ghok && gc >= 0 && gc < IW)
                                v = src[rr * IW + cc];
                            dst[rr * 38 + cc] = v;
                        }
                    }
                }
            }
        }
        // ---- weights: rows wid,wid+8,... cols lane+32k; coalesced, div-free ----
        {
            const float* src = w_src0 + ic0 * 9;
#pragma unroll
            for (int rowi = 0; rowi < 8; rowi++) {
                const int row = wid + rowi * 8;
                const float* s = src + (size_t)rowi * 8 * 4608;
#pragma unroll
                for (int k = 0; k < 5; k++) {
                    const int c = lane + 32 * k;
                    if (c < 144) s_w[c * WS + row] = s[c];
                }
            }
        }
        __syncthreads();

#pragma unroll 4
        for (int icl = 0; icl < 16; icl++) {
#pragma unroll
            for (int ky = 0; ky < 3; ky++) {
                float xin[6];
#pragma unroll
                for (int t = 0; t < 6; t++)
                    xin[t] = in_base[(icl * 4 + ky) * 38 + t];
#pragma unroll
                for (int kx = 0; kx < 3; kx++) {
                    const int ick = icl * 9 + ky * 3 + kx;
                    const float4 w4 = *(const float4*)&w_base[ick * WS];
#pragma unroll
                    for (int j = 0; j < 4; j++) {
                        float xv = xin[kx + j];
                        acc[0][j] = fmaf(w4.x, xv, acc[0][j]);
                        acc[1][j] = fmaf(w4.y, xv, acc[1][j]);
                        acc[2][j] = fmaf(w4.z, xv, acc[2][j]);
                        acc[3][j] = fmaf(w4.w, xv, acc[3][j]);
                    }
                }
            }
        }
        __syncthreads();
    }

    const int gh = h0 + r;
    float b0 = bias[oc0 + ogb + 0];
    float b1 = bias[oc0 + ogb + 1];
    float b2 = bias[oc0 + ogb + 2];
    float b3 = bias[oc0 + ogb + 3];
#pragma unroll
    for (int j = 0; j < 4; j++) {
        int gw = w0 + c0 + j;
        float4 v;
        v.x = fmaxf(acc[0][j] + b0, 0.f);
        v.y = fmaxf(acc[1][j] + b1, 0.f);
        v.z = fmaxf(acc[2][j] + b2, 0.f);
        v.w = fmaxf(acc[3][j] + b3, 0.f);
        *(float4*)&g_x[(size_t)(gh * IW + gw) * 512 + oc0 + ogb] = v;
    }
}

// ---------------- stage 2: 1x1 heads + softmax + anchor decode ----------------
#define HEAD_SMEM ((54 * 513 + 16 * 512 + 16 * 64) * 4)

__global__ __launch_bounds__(1024) void head_kernel(
    const float* __restrict__ im_info,
    const float* __restrict__ sw, const float* __restrict__ sb,
    const float* __restrict__ bw, const float* __restrict__ bb)
{
    extern __shared__ float sm[];
    float* s_w = sm;                       // 54*513
    float* s_x = sm + 54 * 513;            // 16*512
    float* s_o = s_x + 16 * 512;           // 16*64

    const int tid = threadIdx.x;
    const int p0 = blockIdx.x * 16;

    for (int idx = tid; idx < 54 * 512; idx += 1024) {
        int oc = idx >> 9, c = idx & 511;
        float v = (oc < 18) ? sw[oc * 512 + c] : bw[(oc - 18) * 512 + c];
        s_w[oc * 513 + c] = v;
    }
    for (int idx = tid; idx < 16 * 512; idx += 1024)
        s_x[idx] = g_x[(size_t)p0 * 512 + idx];
    __syncthreads();

    const int px = tid >> 6, oc = tid & 63;
    if (oc < 54) {
        float acc = 0.f;
        const float* xr = &s_x[px * 512];
        const float* wr = &s_w[oc * 513];
#pragma unroll 8
        for (int c = 0; c < 512; c++) acc = fmaf(xr[c], wr[c], acc);
        acc += (oc < 18) ? sb[oc] : bb[oc - 18];
        s_o[px * 64 + oc] = acc;
    }
    __syncthreads();

    if (tid < 144) {
        const int lpx = tid / 9, a = tid - lpx * 9;
        const float* row = &s_o[lpx * 64];
        float m = row[0];
#pragma unroll
        for (int i = 1; i < 18; i++) m = fmaxf(m, row[i]);
        float den = 0.f;
#pragma unroll
        for (int i = 0; i < 18; i++) den += expf(row[i] - m);
        float prob = expf(row[9 + a] - m) / den;

        float dx = row[18 + a * 4 + 0];
        float dy = row[18 + a * 4 + 1];
        float dw = row[18 + a * 4 + 2];
        float dh = row[18 + a * 4 + 3];

        const int p = p0 + lpx;
        const int hh = p / IW, ww = p - hh * IW;
        const float sx = ww * 16.f, sy = hh * 16.f;
        float ax1 = c_anch[a][0] + sx, ay1 = c_anch[a][1] + sy;
        float ax2 = c_anch[a][2] + sx, ay2 = c_anch[a][3] + sy;
        float aw = ax2 - ax1 + 1.f, ah = ay2 - ay1 + 1.f;
        float cx = ax1 + 0.5f * aw, cy = ay1 + 0.5f * ah;
        float pcx = dx * aw + cx, pcy = dy * ah + cy;
        float pw = expf(dw) * aw, ph = expf(dh) * ah;
        float x1 = pcx - 0.5f * pw, y1 = pcy - 0.5f * ph;
        float x2 = pcx + 0.5f * pw, y2 = pcy + 0.5f * ph;

        const float imh = im_info[0], imw = im_info[1], iscale = im_info[2];
        x1 = fminf(fmaxf(x1, 0.f), imw - 1.f);
        x2 = fminf(fmaxf(x2, 0.f), imw - 1.f);
        y1 = fminf(fmaxf(y1, 0.f), imh - 1.f);
        y2 = fminf(fmaxf(y2, 0.f), imh - 1.f);

        float wsv = x2 - x1 + 1.f, hsv = y2 - y1 + 1.f;
        bool keep = (wsv >= 16.f * iscale) && (hsv >= 16.f * iscale);
        float sc = keep ? prob : NEGV;

        const int gi = p * 9 + a;
        g_props[gi * 4 + 0] = x1;
        g_props[gi * 4 + 1] = y1;
        g_props[gi * 4 + 2] = x2;
        g_props[gi * 4 + 3] = y2;

        unsigned int u = __float_as_uint(sc);
        u = (u & 0x80000000u) ? ~u : (u | 0x80000000u);
        g_keys[gi] = ((unsigned long long)u << 32) | (unsigned int)(~(unsigned int)gi);
    }
}

// ---------------- stage 3: exact 64-bit radix select ----------------
__global__ __launch_bounds__(256) void hist_pass(int pass) {
    __shared__ unsigned int sh[256];
    if (threadIdx.x < 256) sh[threadIdx.x] = 0u;
    __syncthreads();
    const unsigned long long prefix = g_prefix;
    const int shift = pass * 8;
    for (int i = blockIdx.x * blockDim.x + threadIdx.x; i < NANCH; i += gridDim.x * blockDim.x) {
        unsigned long long k = g_keys[i];
        bool match = (pass == 7) || ((k >> (shift + 8)) == prefix);
        if (match) atomicAdd(&sh[(unsigned int)(k >> shift) & 255u], 1u);
    }
    __syncthreads();
    if (threadIdx.x < 256 && sh[threadIdx.x]) atomicAdd(&g_hist[threadIdx.x], sh[threadIdx.x]);
}

__global__ __launch_bounds__(256) void select_pass(int pass) {
    __shared__ unsigned int c[256];
    const int d = threadIdx.x;
    c[d] = g_hist[d];
    __syncthreads();
#pragma unroll
    for (int off = 1; off < 256; off <<= 1) {
        unsigned int add = (d + off < 256) ? c[d + off] : 0u;
        __syncthreads();
        c[d] += add;
        __syncthreads();
    }
    const unsigned int rank = (unsigned int)g_rank;
    unsigned int cumd  = c[d];
    unsigned int cumd1 = (d < 255) ? c[d + 1] : 0u;
    if (cumd >= rank && cumd1 < rank) {
        g_prefix = (g_prefix << 8) | (unsigned long long)d;
        g_rank = (int)(rank - cumd1);
        if (pass == 0) g_counter = 0u;
    }
    g_hist[d] = 0u;
}

__global__ __launch_bounds__(256) void compact_k() {
    const unsigned long long T = g_prefix;  // exact rank-6000 key (keys unique)
    for (int i = blockIdx.x * blockDim.x + threadIdx.x; i < NANCH; i += gridDim.x * blockDim.x) {
        unsigned long long k = g_keys[i];
        if (k >= T) {
            unsigned int p = atomicAdd(&g_counter, 1u);
            if (p < PRE_NMS) g_cand[p] = k;
        }
    }
}

// ---------------- stage 4: bitonic sort of 6000 (pad 8192) ----------------
__global__ __launch_bounds__(1024) void sort_k() {
    extern __shared__ unsigned long long sk[];  // 8192 * 8B = 64 KB
    const int tid = threadIdx.x;
    for (int i = tid; i < 8192; i += 1024)
        sk[i] = (i < PRE_NMS) ? g_cand[i] : 0ull;
    __syncthreads();
    for (int k = 2; k <= 8192; k <<= 1) {
        for (int j = k >> 1; j > 0; j >>= 1) {
            for (int t = tid; t < 4096; t += 1024) {
                int i = (t << 1) - (t & (j - 1));
                int l = i + j;
                unsigned long long a = sk[i], b = sk[l];
                bool desc = ((i & k) == 0);
                if ((a < b) == desc) { sk[i] = b; sk[l] = a; }
            }
            __syncthreads();
        }
    }
    for (int i = tid; i < PRE_NMS; i += 1024) g_sorted[i] = sk[i];
}

// ---------------- stage 5a: decode sorted keys -> boxes/areas/nvalid ----------------
__global__ __launch_bounds__(1024) void decode_k() {
    int i = blockIdx.x * 1024 + threadIdx.x;
    if (i >= PRE_NMS) return;
    unsigned long long k = g_sorted[i];
    unsigned int idx = ~(unsigned int)(k & 0xffffffffull);
    unsigned int u = (unsigned int)(k >> 32);
    unsigned int ob = (u & 0x80000000u) ? (u & 0x7fffffffu) : ~u;
    float sc = __uint_as_float(ob);
    float a0 = g_props[idx * 4 + 0];
    float a1 = g_props[idx * 4 + 1];
    float a2 = g_props[idx * 4 + 2];
    float a3 = g_props[idx * 4 + 3];
    g_bx[i * 4 + 0] = a0;
    g_bx[i * 4 + 1] = a1;
    g_bx[i * 4 + 2] = a2;
    g_bx[i * 4 + 3] = a3;
    g_ar[i] = (a2 - a0 + 1.f) * (a3 - a1 + 1.f);
    if (!(sc > NEGV * 0.5f)) atomicMin(&g_nvalid, i);
}

// ---------------- stage 5b: all-pairs suppression masks ----------------
__global__ __launch_bounds__(64) void mask_k() {
    const int jb = blockIdx.x, ib = blockIdx.y;
    const int t = threadIdx.x;
    __shared__ float jx1[64], jy1[64], jx2[64], jy2[64], jar[64];

    const int j0 = jb * 64;
    const int jn = min(64, PRE_NMS - j0);
    if (t < jn) {
        jx1[t] = g_bx[(j0 + t) * 4 + 0];
        jy1[t] = g_bx[(j0 + t) * 4 + 1];
        jx2[t] = g_bx[(j0 + t) * 4 + 2];
        jy2[t] = g_bx[(j0 + t) * 4 + 3];
        jar[t] = g_ar[j0 + t];
    }
    __syncthreads();

    const int i = ib * 64 + t;
    if (i >= PRE_NMS) return;
    unsigned long long bits = 0ull;
    if (jb >= ib) {   // lower-triangle blocks: all j <= i -> bits stay 0
        float x1 = g_bx[i * 4 + 0], y1 = g_bx[i * 4 + 1];
        float x2 = g_bx[i * 4 + 2], y2 = g_bx[i * 4 + 3];
        float a  = g_ar[i];
        for (int jj = 0; jj < jn; jj++) {
            if (j0 + jj > i) {
                float xx1 = fmaxf(x1, jx1[jj]);
                float yy1 = fmaxf(y1, jy1[jj]);
                float xx2 = fminf(x2, jx2[jj]);
                float yy2 = fminf(y2, jy2[jj]);
                float inter = fmaxf(xx2 - xx1 + 1.f, 0.f) * fmaxf(yy2 - yy1 + 1.f, 0.f);
                float iou = inter / (a + jar[jj] - inter);
                if (iou > 0.7f) bits |= (1ull << jj);
            }
        }
    }
    g_mask[(size_t)i * NB + jb] = bits;
}

// ---------------- stage 5c: single-warp greedy collect ----------------
__global__ __launch_bounds__(32) void collect_k(float* __restrict__ out) {
    const int lane = threadIdx.x;                 // 32 threads, one warp
    unsigned long long rem[3] = {0ull, 0ull, 0ull};  // lane owns words lane, lane+32, lane+64
    const int nvalid = g_nvalid;
    int kept = 0;
    int w = 0;
    while (w < NB && kept < POST_NMS) {
        const int owner = w & 31, slot = w >> 5;
        long long hi = (long long)nvalid - (long long)w * 64;
        unsigned long long vm = (hi <= 0) ? 0ull : (hi >= 64 ? ~0ull : ((1ull << hi) - 1ull));
        unsigned long long mine = rem[slot];
        unsigned long long live = __shfl_sync(0xffffffffu, ~mine, owner) & vm;
        if (live == 0ull) { w++; continue; }
        const int b = __ffsll((long long)live) - 1;
        const int i = w * 64 + b;
        if (lane == 0) out[kept * 5 + 0] = 0.f;
        if (lane >= 1 && lane <= 4) out[kept * 5 + lane] = g_bx[i * 4 + (lane - 1)];
        kept++;
#pragma unroll
        for (int s = 0; s < 3; s++) {
            int wd = lane + 32 * s;
            if (wd < NB) rem[s] |= g_mask[(size_t)i * NB + wd];
        }
        if (lane == owner) rem[slot] |= (1ull << b);
    }
    for (int q = kept * 5 + lane; q < POST_NMS * 5; q += 32) out[q] = 0.f;
}

// ---------------- launch ----------------
extern "C" void kernel_launch(void* const* d_in, const int* in_sizes, int n_in,
                              void* d_out, int out_size) {
    const float* feat    = (const float*)d_in[0];
    const float* im_info = (const float*)d_in[1];
    const float* c1w     = (const float*)d_in[2];
    const float* c1b     = (const float*)d_in[3];
    const float* sw      = (const float*)d_in[4];
    const float* sb      = (const float*)d_in[5];
    const float* bw      = (const float*)d_in[6];
    const float* bb      = (const float*)d_in[7];
    float* out = (float*)d_out;

    cudaFuncSetAttribute(head_kernel, cudaFuncAttributeMaxDynamicSharedMemorySize, HEAD_SMEM);
    cudaFuncSetAttribute(sort_k, cudaFuncAttributeMaxDynamicSharedMemorySize, 8192 * 8);

    // 3 pre-kernels: state init + aligns ncu (-s 5, 2 harness launches) onto conv
    init1<<<1, 1>>>();
    init2<<<1, 1>>>();
    zero_hist<<<1, 256>>>();

    conv3x3_relu<<<dim3(5, 60, 8), 256>>>(feat, c1w, c1b);
    head_kernel<<<NPIX / 16, 1024, HEAD_SMEM>>>(im_info, sw, sb, bw, bb);
    for (int pass = 7; pass >= 0; pass--) {
        hist_pass<<<256, 256>>>(pass);
        select_pass<<<1, 256>>>(pass);
    }
    compact_k<<<128, 256>>>();
    sort_k<<<1, 1024, 8192 * 8>>>();
    decode_k<<<(PRE_NMS + 1023) / 1024, 1024>>>();
    mask_k<<<dim3(NB, NB), 64>>>();
    collect_k<<<1, 32>>>(out);
}

// round 17
// speedup vs baseline: 1.1934x; 1.0817x over previous
#include <cuda_runtime.h>
#include <cstdint>

#define IH 120
#define IW 160
#define NPIX (IH*IW)
#define NANCH (NPIX*9)
#define PRE_NMS 6000
#define POST_NMS 300
#define NEGV (-1000000000.0f)
#define NB 94                       // ceil(6000/64) mask words per row

// ---------------- device scratch ----------------
__device__ float g_x[NPIX * 512];            // conv1 output, [pixel][channel]
__device__ float g_props[NANCH * 4];
__device__ unsigned long long g_keys[NANCH];
__device__ unsigned long long g_cand[PRE_NMS + 64];
__device__ unsigned long long g_sorted[PRE_NMS + 64];
__device__ unsigned int g_hist[256];
__device__ unsigned long long g_prefix;
__device__ int g_rank;
__device__ unsigned int g_counter;
__device__ unsigned long long g_mask[(size_t)PRE_NMS * NB];  // suppression bitmasks
__device__ float g_bx[PRE_NMS * 4];          // sorted, decoded boxes
__device__ float g_ar[PRE_NMS];              // areas
__device__ int g_nvalid;                     // first index with score <= NEG/2

__constant__ float c_anch[9][4] = {
    {-84.f,  -40.f,  99.f,  55.f},
    {-176.f, -88.f,  191.f, 103.f},
    {-360.f, -184.f, 375.f, 199.f},
    {-56.f,  -56.f,  71.f,  71.f},
    {-120.f, -120.f, 135.f, 135.f},
    {-248.f, -248.f, 263.f, 263.f},
    {-36.f,  -80.f,  51.f,  95.f},
    {-80.f,  -168.f, 95.f,  183.f},
    {-168.f, -344.f, 183.f, 359.f}
};

// ---------------- pre-kernels (state init; also put conv at ncu slot 5) ----------------
__global__ void init1() { g_prefix = 0ull; g_rank = PRE_NMS; }
__global__ void init2() { g_counter = 0u; g_nvalid = PRE_NMS; }
__global__ __launch_bounds__(256) void zero_hist() { g_hist[threadIdx.x] = 0u; }

// ---------------- stage 1: 3x3 conv 512->512 + bias + relu ----------------
// Per-output FMA chain is EXACTLY the verified order (ic chunks of 16 ascending
// -> icl -> ky -> kx, serial fmaf) => g_x bit-identical, rel_err == 2.417291e-07.
// NEW: 4oc x 8px per thread (was 4x4). Same 3 weight LDS.128 now feed 96 FMAs
// (weight smem bytes/FMA halved; total LDS 0.92 B/FMA, -39%). Block covers
// 64 oc x 128 px (4 rows x 32 cols). Div-free staging (validated R16).
#define WS 68   // [ick][oc] stride; multiple of 4 => 16B-aligned float4 loads
#define CONV_SMEM ((144 * WS + 16 * 6 * 38) * 4)   // 53,760 B (dynamic)

__global__ __launch_bounds__(256) void conv3x3_relu(
    const float* __restrict__ feat,   // [512][120][160]
    const float* __restrict__ wgt,    // [512][512][3][3]
    const float* __restrict__ bias)   // [512]
{
    extern __shared__ float smc[];
    float* s_w  = smc;                    // [ick 0..143][oc 0..63]
    float* s_in = smc + 144 * WS;         // [icl 0..15][row 0..5] stride 38 (cols 0..33)

    const int tid = threadIdx.x;
    const int bx = blockIdx.x, by = blockIdx.y;
    const int oc0 = blockIdx.z * 64;
    const int pg = tid & 15, og = tid >> 4;
    const int r = pg >> 2, c0 = (pg & 3) << 3;   // r 0..3, c0 0,8,16,24
    const int h0 = by * 4, w0 = bx * 32;
    const int ogb = og << 2;
    const int wid = tid >> 5, lane = tid & 31;

    float acc[4][8];
#pragma unroll
    for (int o = 0; o < 4; o++)
#pragma unroll
        for (int j = 0; j < 8; j++) acc[o][j] = 0.f;

    // div-free staging bases
    const float* w_src0 = wgt + (size_t)(oc0 + wid) * 4608;   // row wid, +8 rows each
    // compute bases
    const float* in_base = &s_in[r * 38 + c0];
    const float* w_base  = &s_w[ogb];

    for (int ic0 = 0; ic0 < 512; ic0 += 16) {
        // ---- input tile: 16 ic x 6 rows x 34 cols (zero padded), div-free ----
        // each warp stages 2 ic planes
        {
#pragma unroll
            for (int icp = 0; icp < 2; icp++) {
                const int icl = wid * 2 + icp;
                const float* src = feat + (size_t)(ic0 + icl) * NPIX
                                        + (h0 - 1) * IW + (w0 - 1);
                float* dst = &s_in[icl * 6 * 38];
#pragma unroll
                for (int rr = 0; rr < 6; rr++) {
                    const int gh = h0 - 1 + rr;
                    const bool ghok = (gh >= 0 && gh < IH);
#pragma unroll
                    for (int k = 0; k < 2; k++) {
                        const int cc = lane + 32 * k;
                        if (cc < 34) {
                            const int gc = w0 - 1 + cc;
                            float v = 0.f;
                            if (ghok && gc >= 0 && gc < IW)
                                v = src[rr * IW + cc];
                            dst[rr * 38 + cc] = v;
                        }
                    }
                }
            }
        }
        // ---- weights: rows wid,wid+8,... cols lane+32k; coalesced, div-free ----
        {
            const float* src = w_src0 + ic0 * 9;
#pragma unroll
            for (int rowi = 0; rowi < 8; rowi++) {
                const int row = wid + rowi * 8;
                const float* s = src + (size_t)rowi * 8 * 4608;
#pragma unroll
                for (int k = 0; k < 5; k++) {
                    const int c = lane + 32 * k;
                    if (c < 144) s_w[c * WS + row] = s[c];
                }
            }
        }
        __syncthreads();

#pragma unroll 4
        for (int icl = 0; icl < 16; icl++) {
#pragma unroll
            for (int ky = 0; ky < 3; ky++) {
                float xin[10];
#pragma unroll
                for (int t = 0; t < 10; t++)
                    xin[t] = in_base[(icl * 6 + ky) * 38 + t];
#pragma unroll
                for (int kx = 0; kx < 3; kx++) {
                    const int ick = icl * 9 + ky * 3 + kx;
                    const float4 w4 = *(const float4*)&w_base[ick * WS];
#pragma unroll
                    for (int j = 0; j < 8; j++) {
                        float xv = xin[kx + j];
                        acc[0][j] = fmaf(w4.x, xv, acc[0][j]);
                        acc[1][j] = fmaf(w4.y, xv, acc[1][j]);
                        acc[2][j] = fmaf(w4.z, xv, acc[2][j]);
                        acc[3][j] = fmaf(w4.w, xv, acc[3][j]);
                    }
                }
            }
        }
        __syncthreads();
    }

    const int gh = h0 + r;
    float b0 = bias[oc0 + ogb + 0];
    float b1 = bias[oc0 + ogb + 1];
    float b2 = bias[oc0 + ogb + 2];
    float b3 = bias[oc0 + ogb + 3];
#pragma unroll
    for (int j = 0; j < 8; j++) {
        int gw = w0 + c0 + j;
        float4 v;
        v.x = fmaxf(acc[0][j] + b0, 0.f);
        v.y = fmaxf(acc[1][j] + b1, 0.f);
        v.z = fmaxf(acc[2][j] + b2, 0.f);
        v.w = fmaxf(acc[3][j] + b3, 0.f);
        *(float4*)&g_x[(size_t)(gh * IW + gw) * 512 + oc0 + ogb] = v;
    }
}

// ---------------- stage 2: 1x1 heads + softmax + anchor decode ----------------
#define HEAD_SMEM ((54 * 513 + 16 * 512 + 16 * 64) * 4)

__global__ __launch_bounds__(1024) void head_kernel(
    const float* __restrict__ im_info,
    const float* __restrict__ sw, const float* __restrict__ sb,
    const float* __restrict__ bw, const float* __restrict__ bb)
{
    extern __shared__ float sm[];
    float* s_w = sm;                       // 54*513
    float* s_x = sm + 54 * 513;            // 16*512
    float* s_o = s_x + 16 * 512;           // 16*64

    const int tid = threadIdx.x;
    const int p0 = blockIdx.x * 16;

    for (int idx = tid; idx < 54 * 512; idx += 1024) {
        int oc = idx >> 9, c = idx & 511;
        float v = (oc < 18) ? sw[oc * 512 + c] : bw[(oc - 18) * 512 + c];
        s_w[oc * 513 + c] = v;
    }
    for (int idx = tid; idx < 16 * 512; idx += 1024)
        s_x[idx] = g_x[(size_t)p0 * 512 + idx];
    __syncthreads();

    const int px = tid >> 6, oc = tid & 63;
    if (oc < 54) {
        float acc = 0.f;
        const float* xr = &s_x[px * 512];
        const float* wr = &s_w[oc * 513];
#pragma unroll 8
        for (int c = 0; c < 512; c++) acc = fmaf(xr[c], wr[c], acc);
        acc += (oc < 18) ? sb[oc] : bb[oc - 18];
        s_o[px * 64 + oc] = acc;
    }
    __syncthreads();

    if (tid < 144) {
        const int lpx = tid / 9, a = tid - lpx * 9;
        const float* row = &s_o[lpx * 64];
        float m = row[0];
#pragma unroll
        for (int i = 1; i < 18; i++) m = fmaxf(m, row[i]);
        float den = 0.f;
#pragma unroll
        for (int i = 0; i < 18; i++) den += expf(row[i] - m);
        float prob = expf(row[9 + a] - m) / den;

        float dx = row[18 + a * 4 + 0];
        float dy = row[18 + a * 4 + 1];
        float dw = row[18 + a * 4 + 2];
        float dh = row[18 + a * 4 + 3];

        const int p = p0 + lpx;
        const int hh = p / IW, ww = p - hh * IW;
        const float sx = ww * 16.f, sy = hh * 16.f;
        float ax1 = c_anch[a][0] + sx, ay1 = c_anch[a][1] + sy;
        float ax2 = c_anch[a][2] + sx, ay2 = c_anch[a][3] + sy;
        float aw = ax2 - ax1 + 1.f, ah = ay2 - ay1 + 1.f;
        float cx = ax1 + 0.5f * aw, cy = ay1 + 0.5f * ah;
        float pcx = dx * aw + cx, pcy = dy * ah + cy;
        float pw = expf(dw) * aw, ph = expf(dh) * ah;
        float x1 = pcx - 0.5f * pw, y1 = pcy - 0.5f * ph;
        float x2 = pcx + 0.5f * pw, y2 = pcy + 0.5f * ph;

        const float imh = im_info[0], imw = im_info[1], iscale = im_info[2];
        x1 = fminf(fmaxf(x1, 0.f), imw - 1.f);
        x2 = fminf(fmaxf(x2, 0.f), imw - 1.f);
        y1 = fminf(fmaxf(y1, 0.f), imh - 1.f);
        y2 = fminf(fmaxf(y2, 0.f), imh - 1.f);

        float wsv = x2 - x1 + 1.f, hsv = y2 - y1 + 1.f;
        bool keep = (wsv >= 16.f * iscale) && (hsv >= 16.f * iscale);
        float sc = keep ? prob : NEGV;

        const int gi = p * 9 + a;
        g_props[gi * 4 + 0] = x1;
        g_props[gi * 4 + 1] = y1;
        g_props[gi * 4 + 2] = x2;
        g_props[gi * 4 + 3] = y2;

        unsigned int u = __float_as_uint(sc);
        u = (u & 0x80000000u) ? ~u : (u | 0x80000000u);
        g_keys[gi] = ((unsigned long long)u << 32) | (unsigned int)(~(unsigned int)gi);
    }
}

// ---------------- stage 3: exact 64-bit radix select ----------------
__global__ __launch_bounds__(256) void hist_pass(int pass) {
    __shared__ unsigned int sh[256];
    if (threadIdx.x < 256) sh[threadIdx.x] = 0u;
    __syncthreads();
    const unsigned long long prefix = g_prefix;
    const int shift = pass * 8;
    for (int i = blockIdx.x * blockDim.x + threadIdx.x; i < NANCH; i += gridDim.x * blockDim.x) {
        unsigned long long k = g_keys[i];
        bool match = (pass == 7) || ((k >> (shift + 8)) == prefix);
        if (match) atomicAdd(&sh[(unsigned int)(k >> shift) & 255u], 1u);
    }
    __syncthreads();
    if (threadIdx.x < 256 && sh[threadIdx.x]) atomicAdd(&g_hist[threadIdx.x], sh[threadIdx.x]);
}

__global__ __launch_bounds__(256) void select_pass(int pass) {
    __shared__ unsigned int c[256];
    const int d = threadIdx.x;
    c[d] = g_hist[d];
    __syncthreads();
#pragma unroll
    for (int off = 1; off < 256; off <<= 1) {
        unsigned int add = (d + off < 256) ? c[d + off] : 0u;
        __syncthreads();
        c[d] += add;
        __syncthreads();
    }
    const unsigned int rank = (unsigned int)g_rank;
    unsigned int cumd  = c[d];
    unsigned int cumd1 = (d < 255) ? c[d + 1] : 0u;
    if (cumd >= rank && cumd1 < rank) {
        g_prefix = (g_prefix << 8) | (unsigned long long)d;
        g_rank = (int)(rank - cumd1);
        if (pass == 0) g_counter = 0u;
    }
    g_hist[d] = 0u;
}

__global__ __launch_bounds__(256) void compact_k() {
    const unsigned long long T = g_prefix;  // exact rank-6000 key (keys unique)
    for (int i = blockIdx.x * blockDim.x + threadIdx.x; i < NANCH; i += gridDim.x * blockDim.x) {
        unsigned long long k = g_keys[i];
        if (k >= T) {
            unsigned int p = atomicAdd(&g_counter, 1u);
            if (p < PRE_NMS) g_cand[p] = k;
        }
    }
}

// ---------------- stage 4: bitonic sort of 6000 (pad 8192) ----------------
__global__ __launch_bounds__(1024) void sort_k() {
    extern __shared__ unsigned long long sk[];  // 8192 * 8B = 64 KB
    const int tid = threadIdx.x;
    for (int i = tid; i < 8192; i += 1024)
        sk[i] = (i < PRE_NMS) ? g_cand[i] : 0ull;
    __syncthreads();
    for (int k = 2; k <= 8192; k <<= 1) {
        for (int j = k >> 1; j > 0; j >>= 1) {
            for (int t = tid; t < 4096; t += 1024) {
                int i = (t << 1) - (t & (j - 1));
                int l = i + j;
                unsigned long long a = sk[i], b = sk[l];
                bool desc = ((i & k) == 0);
                if ((a < b) == desc) { sk[i] = b; sk[l] = a; }
            }
            __syncthreads();
        }
    }
    for (int i = tid; i < PRE_NMS; i += 1024) g_sorted[i] = sk[i];
}

// ---------------- stage 5a: decode sorted keys -> boxes/areas/nvalid ----------------
__global__ __launch_bounds__(1024) void decode_k() {
    int i = blockIdx.x * 1024 + threadIdx.x;
    if (i >= PRE_NMS) return;
    unsigned long long k = g_sorted[i];
    unsigned int idx = ~(unsigned int)(k & 0xffffffffull);
    unsigned int u = (unsigned int)(k >> 32);
    unsigned int ob = (u & 0x80000000u) ? (u & 0x7fffffffu) : ~u;
    float sc = __uint_as_float(ob);
    float a0 = g_props[idx * 4 + 0];
    float a1 = g_props[idx * 4 + 1];
    float a2 = g_props[idx * 4 + 2];
    float a3 = g_props[idx * 4 + 3];
    g_bx[i * 4 + 0] = a0;
    g_bx[i * 4 + 1] = a1;
    g_bx[i * 4 + 2] = a2;
    g_bx[i * 4 + 3] = a3;
    g_ar[i] = (a2 - a0 + 1.f) * (a3 - a1 + 1.f);
    if (!(sc > NEGV * 0.5f)) atomicMin(&g_nvalid, i);
}

// ---------------- stage 5b: all-pairs suppression masks ----------------
__global__ __launch_bounds__(64) void mask_k() {
    const int jb = blockIdx.x, ib = blockIdx.y;
    const int t = threadIdx.x;
    __shared__ float jx1[64], jy1[64], jx2[64], jy2[64], jar[64];

    const int j0 = jb * 64;
    const int jn = min(64, PRE_NMS - j0);
    if (t < jn) {
        jx1[t] = g_bx[(j0 + t) * 4 + 0];
        jy1[t] = g_bx[(j0 + t) * 4 + 1];
        jx2[t] = g_bx[(j0 + t) * 4 + 2];
        jy2[t] = g_bx[(j0 + t) * 4 + 3];
        jar[t] = g_ar[j0 + t];
    }
    __syncthreads();

    const int i = ib * 64 + t;
    if (i >= PRE_NMS) return;
    unsigned long long bits = 0ull;
    if (jb >= ib) {   // lower-triangle blocks: all j <= i -> bits stay 0
        float x1 = g_bx[i * 4 + 0], y1 = g_bx[i * 4 + 1];
        float x2 = g_bx[i * 4 + 2], y2 = g_bx[i * 4 + 3];
        float a  = g_ar[i];
        for (int jj = 0; jj < jn; jj++) {
            if (j0 + jj > i) {
                float xx1 = fmaxf(x1, jx1[jj]);
                float yy1 = fmaxf(y1, jy1[jj]);
                float xx2 = fminf(x2, jx2[jj]);
                float yy2 = fminf(y2, jy2[jj]);
                float inter = fmaxf(xx2 - xx1 + 1.f, 0.f) * fmaxf(yy2 - yy1 + 1.f, 0.f);
                float iou = inter / (a + jar[jj] - inter);
                if (iou > 0.7f) bits |= (1ull << jj);
            }
        }
    }
    g_mask[(size_t)i * NB + jb] = bits;
}

// ---------------- stage 5c: single-warp greedy collect ----------------
__global__ __launch_bounds__(32) void collect_k(float* __restrict__ out) {
    const int lane = threadIdx.x;                 // 32 threads, one warp
    unsigned long long rem[3] = {0ull, 0ull, 0ull};  // lane owns words lane, lane+32, lane+64
    const int nvalid = g_nvalid;
    int kept = 0;
    int w = 0;
    while (w < NB && kept < POST_NMS) {
        const int owner = w & 31, slot = w >> 5;
        long long hi = (long long)nvalid - (long long)w * 64;
        unsigned long long vm = (hi <= 0) ? 0ull : (hi >= 64 ? ~0ull : ((1ull << hi) - 1ull));
        unsigned long long mine = rem[slot];
        unsigned long long live = __shfl_sync(0xffffffffu, ~mine, owner) & vm;
        if (live == 0ull) { w++; continue; }
        const int b = __ffsll((long long)live) - 1;
        const int i = w * 64 + b;
        if (lane == 0) out[kept * 5 + 0] = 0.f;
        if (lane >= 1 && lane <= 4) out[kept * 5 + lane] = g_bx[i * 4 + (lane - 1)];
        kept++;
#pragma unroll
        for (int s = 0; s < 3; s++) {
            int wd = lane + 32 * s;
            if (wd < NB) rem[s] |= g_mask[(size_t)i * NB + wd];
        }
        if (lane == owner) rem[slot] |= (1ull << b);
    }
    for (int q = kept * 5 + lane; q < POST_NMS * 5; q += 32) out[q] = 0.f;
}

// ---------------- launch ----------------
extern "C" void kernel_launch(void* const* d_in, const int* in_sizes, int n_in,
                              void* d_out, int out_size) {
    const float* feat    = (const float*)d_in[0];
    const float* im_info = (const float*)d_in[1];
    const float* c1w     = (const float*)d_in[2];
    const float* c1b     = (const float*)d_in[3];
    const float* sw      = (const float*)d_in[4];
    const float* sb      = (const float*)d_in[5];
    const float* bw      = (const float*)d_in[6];
    const float* bb      = (const float*)d_in[7];
    float* out = (float*)d_out;

    cudaFuncSetAttribute(conv3x3_relu, cudaFuncAttributeMaxDynamicSharedMemorySize, CONV_SMEM);
    cudaFuncSetAttribute(head_kernel, cudaFuncAttributeMaxDynamicSharedMemorySize, HEAD_SMEM);
    cudaFuncSetAttribute(sort_k, cudaFuncAttributeMaxDynamicSharedMemorySize, 8192 * 8);

    // 3 pre-kernels: state init + aligns ncu (-s 5, 2 harness launches) onto conv
    init1<<<1, 1>>>();
    init2<<<1, 1>>>();
    zero_hist<<<1, 256>>>();

    conv3x3_relu<<<dim3(5, 30, 8), 256, CONV_SMEM>>>(feat, c1w, c1b);
    head_kernel<<<NPIX / 16, 1024, HEAD_SMEM>>>(im_info, sw, sb, bw, bb);
    for (int pass = 7; pass >= 0; pass--) {
        hist_pass<<<256, 256>>>(pass);
        select_pass<<<1, 256>>>(pass);
    }
    compact_k<<<128, 256>>>();
    sort_k<<<1, 1024, 8192 * 8>>>();
    decode_k<<<(PRE_NMS + 1023) / 1024, 1024>>>();
    mask_k<<<dim3(NB, NB), 64>>>();
    collect_k<<<1, 32>>>(out);
}